// round 1
// baseline (speedup 1.0000x reference)
#include <cuda_runtime.h>

#define D 128
#define NREL_HALF 24
#define BN_EPS 1e-5f

// Scratch: device globals (no allocations allowed in kernel_launch).
__device__ float g_feats[100000 * 128];   // 51.2 MB: x @ W
__device__ float g_stats[512];            // [0:128) col sums, [128:256) col sumsq,
                                          // [256:384) scale, [384:512) shift

// ---------------------------------------------------------------------------
// Zero the aggregation buffer (d_out doubles as agg) + stats.
// ---------------------------------------------------------------------------
__global__ void zero_kernel(float4* __restrict__ agg, int n4) {
    int i = blockIdx.x * blockDim.x + threadIdx.x;
    float4 z = make_float4(0.f, 0.f, 0.f, 0.f);
    if (i < n4) agg[i] = z;
    if (i < 128) ((float4*)g_stats)[i] = z;
}

// ---------------------------------------------------------------------------
// feats = x @ W   (100000 x 128) @ (128 x 128), fp32.
// Each block handles a 64-row tile and one 64-column half of W (32 KB smem).
// Thread = 4 cols (float4) x 4 rows -> 16 accumulators.
// ---------------------------------------------------------------------------
__global__ void gemm_kernel(const float* __restrict__ x,
                            const float* __restrict__ w,
                            int n_rows) {
    __shared__ float4 Ws[128 * 16];  // W[k][ch*64 + c], 32 KB
    const int ch  = blockIdx.y;      // column half: 0 or 1
    const int tid = threadIdx.x;

    for (int i = tid; i < 128 * 16; i += 256) {
        int k = i >> 4, c4 = i & 15;
        Ws[i] = ((const float4*)(w + k * 128 + ch * 64))[c4];
    }
    __syncthreads();

    const int cg = tid & 15;         // which float4 of the 64-col half
    const int rg = tid >> 4;         // 0..15 -> rows rg*4 .. rg*4+3
    const int row0 = blockIdx.x * 64 + rg * 4;
    if (row0 >= n_rows) return;      // n_rows % 4 == 0, so all 4 rows valid

    const float* xr = x + (size_t)row0 * 128;
    float4 a0 = make_float4(0.f, 0.f, 0.f, 0.f);
    float4 a1 = a0, a2 = a0, a3 = a0;

#pragma unroll 8
    for (int k = 0; k < 128; k++) {
        float4 wv = Ws[k * 16 + cg];
        float x0 = __ldg(xr + k);
        float x1 = __ldg(xr + 128 + k);
        float x2 = __ldg(xr + 256 + k);
        float x3 = __ldg(xr + 384 + k);
        a0.x += x0 * wv.x; a0.y += x0 * wv.y; a0.z += x0 * wv.z; a0.w += x0 * wv.w;
        a1.x += x1 * wv.x; a1.y += x1 * wv.y; a1.z += x1 * wv.z; a1.w += x1 * wv.w;
        a2.x += x2 * wv.x; a2.y += x2 * wv.y; a2.z += x2 * wv.z; a2.w += x2 * wv.w;
        a3.x += x3 * wv.x; a3.y += x3 * wv.y; a3.z += x3 * wv.z; a3.w += x3 * wv.w;
    }

    float4* fout = (float4*)g_feats + (size_t)row0 * 32 + ch * 16 + cg;
    fout[0]  = a0;
    fout[32] = a1;
    fout[64] = a2;
    fout[96] = a3;
}

// ---------------------------------------------------------------------------
// Edge scatter: one warp per edge. Each lane handles one float4 (4 of 128).
// msg = feats[src] * (alpha[t] + alpha[t^]), reduced into agg[dst] via
// red.global.add.v4.f32 (REDG.128, no return value).
// ---------------------------------------------------------------------------
__global__ void scatter_kernel(const int* __restrict__ src,
                               const int* __restrict__ dst,
                               const int* __restrict__ et,
                               const float* __restrict__ alpha,
                               float* __restrict__ agg,
                               int n_edges) {
    int gtid = blockIdx.x * blockDim.x + threadIdx.x;
    int e    = gtid >> 5;
    int lane = gtid & 31;
    if (e >= n_edges) return;

    int s = __ldg(src + e);
    int d = __ldg(dst + e);
    int t = __ldg(et + e);
    int tt = (t >= NREL_HALF) ? t - NREL_HALF : t + NREL_HALF;
    float alp = __ldg(alpha + t) + __ldg(alpha + tt);

    float4 f = *((const float4*)g_feats + (size_t)s * 32 + lane);
    float* ap = agg + (size_t)d * 128 + lane * 4;
    asm volatile("red.global.add.v4.f32 [%0], {%1, %2, %3, %4};"
                 :: "l"(ap), "f"(f.x * alp), "f"(f.y * alp),
                    "f"(f.z * alp), "f"(f.w * alp)
                 : "memory");
}

// ---------------------------------------------------------------------------
// Column-wise sum / sumsq partials, combined with fp32 atomics.
// ---------------------------------------------------------------------------
__global__ void stats_kernel(const float* __restrict__ agg, int n_rows) {
    int c = threadIdx.x;  // 128 threads, one per column
    float sum = 0.f, sq = 0.f;
    for (int r = blockIdx.x; r < n_rows; r += gridDim.x) {
        float v = agg[(size_t)r * 128 + c];
        sum += v;
        sq  += v * v;
    }
    atomicAdd(&g_stats[c], sum);
    atomicAdd(&g_stats[128 + c], sq);
}

// ---------------------------------------------------------------------------
// Fold mean/var/gamma/beta into per-column scale & shift.
// ---------------------------------------------------------------------------
__global__ void finalize_kernel(const float* __restrict__ gamma,
                                const float* __restrict__ beta,
                                float inv_n) {
    int c = threadIdx.x;
    float mean  = g_stats[c] * inv_n;
    float var   = g_stats[128 + c] * inv_n - mean * mean;
    float scale = rsqrtf(var + BN_EPS) * gamma[c];
    g_stats[256 + c] = scale;
    g_stats[384 + c] = beta[c] - mean * scale;
}

// ---------------------------------------------------------------------------
// In-place normalize: out = agg * scale + shift (vectorized).
// ---------------------------------------------------------------------------
__global__ void norm_kernel(float4* __restrict__ out, int n4) {
    int i = blockIdx.x * blockDim.x + threadIdx.x;
    if (i >= n4) return;
    int c4 = i & 31;
    float4 sc = ((const float4*)(g_stats + 256))[c4];
    float4 sh = ((const float4*)(g_stats + 384))[c4];
    float4 v = out[i];
    v.x = v.x * sc.x + sh.x;
    v.y = v.y * sc.y + sh.y;
    v.z = v.z * sc.z + sh.z;
    v.w = v.w * sc.w + sh.w;
    out[i] = v;
}

// ---------------------------------------------------------------------------
// Inputs (metadata order): x, weight, alpha, gamma, beta, src, dst, edge_type
// ---------------------------------------------------------------------------
extern "C" void kernel_launch(void* const* d_in, const int* in_sizes, int n_in,
                              void* d_out, int out_size) {
    const float* x     = (const float*)d_in[0];
    const float* w     = (const float*)d_in[1];
    const float* alpha = (const float*)d_in[2];
    const float* gamma = (const float*)d_in[3];
    const float* beta  = (const float*)d_in[4];
    const int*   src   = (const int*)d_in[5];
    const int*   dst   = (const int*)d_in[6];
    const int*   et    = (const int*)d_in[7];
    float* out = (float*)d_out;

    int n_edges = in_sizes[5];
    int n_rows  = in_sizes[0] / D;   // 100000
    int n4      = out_size / 4;      // 3.2M float4

    zero_kernel<<<(n4 + 255) / 256, 256>>>((float4*)out, n4);

    gemm_kernel<<<dim3((n_rows + 63) / 64, 2), 256>>>(x, w, n_rows);

    long long sthreads = (long long)n_edges * 32;
    int sblocks = (int)((sthreads + 255) / 256);
    scatter_kernel<<<sblocks, 256>>>(src, dst, et, alpha, out, n_edges);

    stats_kernel<<<1024, 128>>>(out, n_rows);
    finalize_kernel<<<1, 128>>>(gamma, beta, 1.0f / (float)n_rows);
    norm_kernel<<<(n4 + 255) / 256, 256>>>((float4*)out, n4);
}

// round 3
// speedup vs baseline: 1.7484x; 1.7484x over previous
#include <cuda_runtime.h>

#define D 128
#define NREL_HALF 24
#define BN_EPS 1e-5f
#define MAX_NODES 100000
#define MAX_EDGES 1600000
#define SCAN_CHUNK 2048   // elements per scanA block (256 threads * 8)

// Scratch: device globals (no allocations allowed).
__device__ float g_feats[MAX_NODES * 128];   // 51.2 MB: x @ W
__device__ int   g_cnt[MAX_NODES];           // per-dst degree
__device__ int   g_off[MAX_NODES + 1];       // CSR offsets
__device__ int   g_cursor[MAX_NODES];        // reorder cursors
__device__ int   g_esrc[MAX_EDGES];          // CSR: src per slot
__device__ float g_ealp[MAX_EDGES];          // CSR: premultiplied alpha per slot
__device__ int   g_bsums[64];                // scan block sums (49 used)
__device__ float g_stats[512];               // sums / sumsq / scale / shift

// ---------------------------------------------------------------------------
// Zero degree counters + stats (tiny).
// ---------------------------------------------------------------------------
__global__ void zero_kernel(int n_nodes) {
    int i = blockIdx.x * blockDim.x + threadIdx.x;
    if (i < n_nodes) g_cnt[i] = 0;
    if (i < 512) g_stats[i] = 0.f;
}

// ---------------------------------------------------------------------------
// feats = x @ W   (N x 128) @ (128 x 128), fp32.
// Block: 64-row tile x one 64-col half. Thread: 4 rows x float4 cols.
// x loaded as float4 (4 k at a time).
// ---------------------------------------------------------------------------
__global__ void gemm_kernel(const float* __restrict__ x,
                            const float* __restrict__ w,
                            int n_rows) {
    __shared__ float4 Ws[128 * 16];  // W[k][ch*64 + c], 32 KB
    const int ch  = blockIdx.y;
    const int tid = threadIdx.x;

    for (int i = tid; i < 128 * 16; i += 256) {
        int k = i >> 4, c4 = i & 15;
        Ws[i] = ((const float4*)(w + k * 128 + ch * 64))[c4];
    }
    __syncthreads();

    const int cg = tid & 15;
    const int rg = tid >> 4;
    const int row0 = blockIdx.x * 64 + rg * 4;
    if (row0 >= n_rows) return;

    const float4* xr = (const float4*)(x + (size_t)row0 * 128);  // 32 float4/row
    float4 a0 = make_float4(0.f, 0.f, 0.f, 0.f);
    float4 a1 = a0, a2 = a0, a3 = a0;

#pragma unroll 4
    for (int kk = 0; kk < 32; kk++) {
        float4 x0 = __ldg(xr + kk);
        float4 x1 = __ldg(xr + 32 + kk);
        float4 x2 = __ldg(xr + 64 + kk);
        float4 x3 = __ldg(xr + 96 + kk);
        const float xs0[4] = {x0.x, x0.y, x0.z, x0.w};
        const float xs1[4] = {x1.x, x1.y, x1.z, x1.w};
        const float xs2[4] = {x2.x, x2.y, x2.z, x2.w};
        const float xs3[4] = {x3.x, x3.y, x3.z, x3.w};
#pragma unroll
        for (int j = 0; j < 4; j++) {
            float4 wv = Ws[(kk * 4 + j) * 16 + cg];
            float v0 = xs0[j], v1 = xs1[j], v2 = xs2[j], v3 = xs3[j];
            a0.x += v0 * wv.x; a0.y += v0 * wv.y; a0.z += v0 * wv.z; a0.w += v0 * wv.w;
            a1.x += v1 * wv.x; a1.y += v1 * wv.y; a1.z += v1 * wv.z; a1.w += v1 * wv.w;
            a2.x += v2 * wv.x; a2.y += v2 * wv.y; a2.z += v2 * wv.z; a2.w += v2 * wv.w;
            a3.x += v3 * wv.x; a3.y += v3 * wv.y; a3.z += v3 * wv.z; a3.w += v3 * wv.w;
        }
    }

    float4* fout = (float4*)g_feats + (size_t)row0 * 32 + ch * 16 + cg;
    fout[0]  = a0;
    fout[32] = a1;
    fout[64] = a2;
    fout[96] = a3;
}

// ---------------------------------------------------------------------------
// Histogram of destinations.
// ---------------------------------------------------------------------------
__global__ void hist_kernel(const int* __restrict__ dst, int n_edges) {
    int e = blockIdx.x * blockDim.x + threadIdx.x;
    if (e < n_edges) atomicAdd(&g_cnt[__ldg(dst + e)], 1);
}

// ---------------------------------------------------------------------------
// Two-level exclusive scan of g_cnt -> g_off (+ block sums).
// ---------------------------------------------------------------------------
__global__ void scanA_kernel(int n) {
    __shared__ int wsum[8];
    int t = threadIdx.x;
    int base = blockIdx.x * SCAN_CHUNK + t * 8;
    int v[8];
    int run = 0;
#pragma unroll
    for (int j = 0; j < 8; j++) {
        int idx = base + j;
        int c = (idx < n) ? g_cnt[idx] : 0;
        v[j] = run;
        run += c;
    }
    int lane = t & 31, w = t >> 5;
    int inc = run;
#pragma unroll
    for (int o = 1; o < 32; o <<= 1) {
        int y = __shfl_up_sync(0xffffffffu, inc, o);
        if (lane >= o) inc += y;
    }
    if (lane == 31) wsum[w] = inc;
    __syncthreads();
    if (t == 0) {
        int s = 0;
#pragma unroll
        for (int i = 0; i < 8; i++) { int c = wsum[i]; wsum[i] = s; s += c; }
        g_bsums[blockIdx.x] = s;
    }
    __syncthreads();
    int excl = inc - run + wsum[w];
#pragma unroll
    for (int j = 0; j < 8; j++) {
        int idx = base + j;
        if (idx < n) g_off[idx] = excl + v[j];
    }
}

__global__ void scanB_kernel(int nb) {
    __shared__ int s[64];
    int t = threadIdx.x;
    if (t < nb) s[t] = g_bsums[t];
    __syncthreads();
    if (t == 0) {
        int r = 0;
        for (int i = 0; i < nb; i++) { int c = s[i]; s[i] = r; r += c; }
    }
    __syncthreads();
    if (t < nb) g_bsums[t] = s[t];
}

__global__ void scanC_kernel(int n, int n_edges) {
    int i = blockIdx.x * blockDim.x + threadIdx.x;
    if (i < n) {
        int o = g_off[i] + g_bsums[i / SCAN_CHUNK];
        g_off[i] = o;
        g_cursor[i] = o;
    }
    if (i == 0) g_off[n] = n_edges;
}

// ---------------------------------------------------------------------------
// Reorder edges into CSR slots; premultiply alpha.
// ---------------------------------------------------------------------------
__global__ void reorder_kernel(const int* __restrict__ src,
                               const int* __restrict__ dst,
                               const int* __restrict__ et,
                               const float* __restrict__ alpha,
                               int n_edges) {
    int e = blockIdx.x * blockDim.x + threadIdx.x;
    if (e >= n_edges) return;
    int d = __ldg(dst + e);
    int pos = atomicAdd(&g_cursor[d], 1);
    int t = __ldg(et + e);
    int tt = (t >= NREL_HALF) ? t - NREL_HALF : t + NREL_HALF;
    g_esrc[pos] = __ldg(src + e);
    g_ealp[pos] = __ldg(alpha + t) + __ldg(alpha + tt);
}

// ---------------------------------------------------------------------------
// Pull-gather: one warp per dst node (grid-stride). Lane owns 4 columns.
// Writes agg row once; accumulates BN stats in registers, flushes per block.
// ---------------------------------------------------------------------------
__global__ void gather_kernel(float4* __restrict__ agg, int n_nodes) {
    const int lane   = threadIdx.x & 31;
    const int gwarp  = (blockIdx.x * blockDim.x + threadIdx.x) >> 5;
    const int nwarps = (gridDim.x * blockDim.x) >> 5;
    const float4* feats4 = (const float4*)g_feats;

    float4 csum = make_float4(0.f, 0.f, 0.f, 0.f);
    float4 csq  = csum;

    for (int d = gwarp; d < n_nodes; d += nwarps) {
        int b = g_off[d], e = g_off[d + 1];
        float4 acc = make_float4(0.f, 0.f, 0.f, 0.f);
        int i = b;
        for (; i + 1 < e; i += 2) {
            int   s0 = __ldg(g_esrc + i);
            int   s1 = __ldg(g_esrc + i + 1);
            float p0 = __ldg(g_ealp + i);
            float p1 = __ldg(g_ealp + i + 1);
            float4 f0 = feats4[(size_t)s0 * 32 + lane];
            float4 f1 = feats4[(size_t)s1 * 32 + lane];
            acc.x += f0.x * p0 + f1.x * p1;
            acc.y += f0.y * p0 + f1.y * p1;
            acc.z += f0.z * p0 + f1.z * p1;
            acc.w += f0.w * p0 + f1.w * p1;
        }
        if (i < e) {
            int   s0 = __ldg(g_esrc + i);
            float p0 = __ldg(g_ealp + i);
            float4 f0 = feats4[(size_t)s0 * 32 + lane];
            acc.x += f0.x * p0;
            acc.y += f0.y * p0;
            acc.z += f0.z * p0;
            acc.w += f0.w * p0;
        }
        agg[(size_t)d * 32 + lane] = acc;
        csum.x += acc.x; csum.y += acc.y; csum.z += acc.z; csum.w += acc.w;
        csq.x  += acc.x * acc.x; csq.y += acc.y * acc.y;
        csq.z  += acc.z * acc.z; csq.w += acc.w * acc.w;
    }

    // Block-level stats reduction: lane L of every warp owns columns 4L..4L+3.
    __shared__ float4 s_sum[256], s_sq[256];
    s_sum[threadIdx.x] = csum;
    s_sq[threadIdx.x]  = csq;
    __syncthreads();
    if (threadIdx.x < 32) {
        float4 ts = make_float4(0.f, 0.f, 0.f, 0.f);
        float4 tq = ts;
        for (int w = 0; w < 8; w++) {
            float4 a = s_sum[w * 32 + threadIdx.x];
            float4 b = s_sq[w * 32 + threadIdx.x];
            ts.x += a.x; ts.y += a.y; ts.z += a.z; ts.w += a.w;
            tq.x += b.x; tq.y += b.y; tq.z += b.z; tq.w += b.w;
        }
        int c = threadIdx.x * 4;
        atomicAdd(&g_stats[c + 0], ts.x);
        atomicAdd(&g_stats[c + 1], ts.y);
        atomicAdd(&g_stats[c + 2], ts.z);
        atomicAdd(&g_stats[c + 3], ts.w);
        atomicAdd(&g_stats[128 + c + 0], tq.x);
        atomicAdd(&g_stats[128 + c + 1], tq.y);
        atomicAdd(&g_stats[128 + c + 2], tq.z);
        atomicAdd(&g_stats[128 + c + 3], tq.w);
    }
}

// ---------------------------------------------------------------------------
// Fold mean/var/gamma/beta into per-column scale & shift.
// ---------------------------------------------------------------------------
__global__ void finalize_kernel(const float* __restrict__ gamma,
                                const float* __restrict__ beta,
                                float inv_n) {
    int c = threadIdx.x;
    float mean  = g_stats[c] * inv_n;
    float var   = g_stats[128 + c] * inv_n - mean * mean;
    float scale = rsqrtf(var + BN_EPS) * gamma[c];
    g_stats[256 + c] = scale;
    g_stats[384 + c] = beta[c] - mean * scale;
}

// ---------------------------------------------------------------------------
// In-place normalize: out = agg * scale + shift.
// ---------------------------------------------------------------------------
__global__ void norm_kernel(float4* __restrict__ out, int n4) {
    int i = blockIdx.x * blockDim.x + threadIdx.x;
    if (i >= n4) return;
    int c4 = i & 31;
    float4 sc = ((const float4*)(g_stats + 256))[c4];
    float4 sh = ((const float4*)(g_stats + 384))[c4];
    float4 v = out[i];
    v.x = v.x * sc.x + sh.x;
    v.y = v.y * sc.y + sh.y;
    v.z = v.z * sc.z + sh.z;
    v.w = v.w * sc.w + sh.w;
    out[i] = v;
}

// ---------------------------------------------------------------------------
// Inputs: x, weight, alpha, gamma, beta, src, dst, edge_type
// ---------------------------------------------------------------------------
extern "C" void kernel_launch(void* const* d_in, const int* in_sizes, int n_in,
                              void* d_out, int out_size) {
    const float* x     = (const float*)d_in[0];
    const float* w     = (const float*)d_in[1];
    const float* alpha = (const float*)d_in[2];
    const float* gamma = (const float*)d_in[3];
    const float* beta  = (const float*)d_in[4];
    const int*   src   = (const int*)d_in[5];
    const int*   dst   = (const int*)d_in[6];
    const int*   et    = (const int*)d_in[7];
    float* out = (float*)d_out;

    int n_edges = in_sizes[5];
    int n_rows  = in_sizes[0] / D;            // 100000
    int n4      = out_size / 4;               // 3.2M float4
    int nscan   = (n_rows + SCAN_CHUNK - 1) / SCAN_CHUNK;  // 49

    zero_kernel<<<(n_rows + 255) / 256, 256>>>(n_rows);

    gemm_kernel<<<dim3((n_rows + 63) / 64, 2), 256>>>(x, w, n_rows);

    hist_kernel<<<(n_edges + 255) / 256, 256>>>(dst, n_edges);
    scanA_kernel<<<nscan, 256>>>(n_rows);
    scanB_kernel<<<1, 64>>>(nscan);
    scanC_kernel<<<(n_rows + 255) / 256, 256>>>(n_rows, n_edges);
    reorder_kernel<<<(n_edges + 255) / 256, 256>>>(src, dst, et, alpha, n_edges);

    gather_kernel<<<1184, 256>>>((float4*)out, n_rows);

    finalize_kernel<<<1, 128>>>(gamma, beta, 1.0f / (float)n_rows);
    norm_kernel<<<(n4 + 255) / 256, 256>>>((float4*)out, n4);
}